// round 14
// baseline (speedup 1.0000x reference)
#include <cuda_runtime.h>
#include <cuda_fp16.h>
#include <math.h>
#include <stdint.h>

// ---------------- problem constants ----------------
#define Bb   2
#define Tt   2048
#define Dd   2048
#define Hh   32
#define Kd   64
#define CH   128
#define NCH  (Tt / CH)          // 16
#define BT   (Bb * Tt)          // 4096
#define TOK  4
#define EPSV 6.4e-4f

// ---------------- scratch (device globals, no cudaMalloc) ----------------
__device__ __half g_xkh[BT * Dd], g_xkl[BT * Dd];
__device__ __half g_xvh[BT * Dd], g_xvl[BT * Dd];
__device__ __half g_xrh[BT * Dd], g_xrl[BT * Dd];
__device__ __half g_xgh[BT * Dd], g_xgl[BT * Dd];
__device__ __half g_yh [BT * Dd], g_yl [BT * Dd];
__device__ __half g_Wrh[Dd * Dd];
__device__ __half g_Wkh[Dd * Dd];
__device__ __half g_Wvh[Dd * Dd];
__device__ __half g_Wgh[Dd * Dd];
__device__ __half g_Woh[Dd * Dd];
__device__ float g_wd[BT * Dd];
__device__ float g_r [BT * Dd];
__device__ float g_k [BT * Dd];
__device__ float g_v [BT * Dd];
__device__ float g_g [BT * Dd];
__device__ float g_cs[Bb * Hh * NCH * Kd * Kd];
__device__ float g_es[Bb * Hh * NCH * Kd * Kd];
__device__ float g_ws[Bb * Hh * NCH * Kd];

__device__ __forceinline__ void split_fp16(float v, __half& h, __half& l) {
    h = __float2half_rn(v);
    l = __float2half_rn(v - __half2float(h));
}

// ---------------- PTX helpers ----------------
#define LDSM4(r0,r1,r2,r3,addr) \
    asm volatile("ldmatrix.sync.aligned.m8n8.x4.shared.b16 {%0,%1,%2,%3}, [%4];" \
        : "=r"(r0),"=r"(r1),"=r"(r2),"=r"(r3) : "r"(addr))

#define MMA16816F(d,a,b) \
    asm volatile("mma.sync.aligned.m16n8k16.row.col.f32.f16.f16.f32 " \
        "{%0,%1,%2,%3},{%4,%5,%6,%7},{%8,%9},{%0,%1,%2,%3};" \
        : "+f"(d[0]),"+f"(d[1]),"+f"(d[2]),"+f"(d[3]) \
        : "r"(a[0]),"r"(a[1]),"r"(a[2]),"r"(a[3]),"r"(b[0]),"r"(b[1]))

#define CP_ASYNC16(dst, src) \
    asm volatile("cp.async.cg.shared.global [%0], [%1], 16;" :: "r"(dst), "l"(src) : "memory")
#define CP_COMMIT() asm volatile("cp.async.commit_group;" ::: "memory")
#define CP_WAIT1()  asm volatile("cp.async.wait_group 1;" ::: "memory")

// =====================================================================
// Batched tensor-core GEMM (mma.sync), 2x fp16 split: C = Ah.Wh + Al.Wh
// 128x128 CTA tile, BK=64, 3-stage cp.async pipeline, 8 warps.
// =====================================================================
#define G_STAGE 32768
#define G_SMEM  (3 * G_STAGE)
#define G_NIT   64

struct GemmArgs {
    const __half* Ah[4];
    const __half* Al[4];
    const __half* Wh[4];
    float* C[4];
    int mode[4];
};

__device__ __forceinline__ void issue_chunk(
    int nx, uint32_t sbase, int m0, int n0, int tid,
    const __half* Ah, const __half* Al, const __half* Wh)
{
    const int pass = nx >> 5;
    const int kk   = (nx & 31) << 6;
    const __half* Ap = pass ? Al : Ah;
    uint32_t sa = sbase + (nx % 3) * G_STAGE;
    uint32_t sb = sa + 16384;
    #pragma unroll
    for (int i = 0; i < 4; i++) {
        int ch = tid + i * 256;
        int r = ch >> 3, c = ch & 7;
        uint32_t soff = r * 128 + ((c ^ (r & 7)) << 4);
        CP_ASYNC16(sa + soff, Ap + (size_t)(m0 + r) * Dd + kk + c * 8);
        CP_ASYNC16(sb + soff, Wh + (size_t)(n0 + r) * Dd + kk + c * 8);
    }
}

__global__ void __launch_bounds__(256) gemm4(GemmArgs ga)
{
    extern __shared__ char gsm[];
    uint32_t sbase;
    asm("{ .reg .u64 t; cvta.to.shared.u64 t, %1; cvt.u32.u64 %0, t; }"
        : "=r"(sbase) : "l"(gsm));

    const int z = blockIdx.z;
    const __half* Ahp = ga.Ah[z];
    const __half* Alp = ga.Al[z];
    const __half* Whp = ga.Wh[z];
    float* Cp = ga.C[z];
    const int mode = ga.mode[z];

    const int tid  = threadIdx.x;
    const int lane = tid & 31;
    const int w    = tid >> 5;
    const int wm   = w >> 2;
    const int wn   = w & 3;
    const int m0   = blockIdx.y * 128;
    const int n0   = blockIdx.x * 128;

    const int rlo = (lane & 7) + ((lane >> 3) & 1) * 8;
    const int lg  = lane >> 4;

    int arow[4], asw[4];
    #pragma unroll
    for (int i = 0; i < 4; i++) {
        int r = wm * 64 + i * 16 + rlo;
        arow[i] = r * 128;
        asw[i]  = r & 7;
    }
    int brow[2], bsw[2];
    #pragma unroll
    for (int jp = 0; jp < 2; jp++) {
        int r = wn * 32 + jp * 16 + rlo;
        brow[jp] = r * 128;
        bsw[jp]  = r & 7;
    }

    float acc[4][4][4];
    #pragma unroll
    for (int i = 0; i < 4; i++)
        #pragma unroll
        for (int j = 0; j < 4; j++)
            #pragma unroll
            for (int q = 0; q < 4; q++) acc[i][j][q] = 0.f;

    issue_chunk(0, sbase, m0, n0, tid, Ahp, Alp, Whp); CP_COMMIT();
    issue_chunk(1, sbase, m0, n0, tid, Ahp, Alp, Whp); CP_COMMIT();

    for (int it = 0; it < G_NIT; it++) {
        CP_WAIT1();
        __syncthreads();

        if (it + 2 < G_NIT)
            issue_chunk(it + 2, sbase, m0, n0, tid, Ahp, Alp, Whp);
        CP_COMMIT();

        uint32_t abase = sbase + (it % 3) * G_STAGE;
        uint32_t bbase = abase + 16384;
        #pragma unroll
        for (int ks = 0; ks < 4; ks++) {
            const int cc = ks * 2 + lg;
            uint32_t a[4][4], b[4][2];
            #pragma unroll
            for (int i = 0; i < 4; i++) {
                uint32_t addr = abase + arow[i] + ((cc ^ asw[i]) << 4);
                LDSM4(a[i][0], a[i][1], a[i][2], a[i][3], addr);
            }
            #pragma unroll
            for (int jp = 0; jp < 2; jp++) {
                uint32_t addr = bbase + brow[jp] + ((cc ^ bsw[jp]) << 4);
                uint32_t t0, t1, t2, t3;
                LDSM4(t0, t1, t2, t3, addr);
                b[2 * jp][0] = t0; b[2 * jp + 1][0] = t1;
                b[2 * jp][1] = t2; b[2 * jp + 1][1] = t3;
            }
            #pragma unroll
            for (int i = 0; i < 4; i++)
                #pragma unroll
                for (int j = 0; j < 4; j++)
                    MMA16816F(acc[i][j], a[i], b[j]);
        }
    }

    #pragma unroll
    for (int i = 0; i < 4; i++) {
        int mr = m0 + wm * 64 + i * 16 + (lane >> 2);
        #pragma unroll
        for (int j = 0; j < 4; j++) {
            int nc = n0 + wn * 32 + j * 8 + (lane & 3) * 2;
            float v0 = acc[i][j][0], v1 = acc[i][j][1];
            float v2 = acc[i][j][2], v3 = acc[i][j][3];
            if (mode == 1) {
                v0 = v0 / (1.f + expf(-v0));
                v1 = v1 / (1.f + expf(-v1));
                v2 = v2 / (1.f + expf(-v2));
                v3 = v3 / (1.f + expf(-v3));
            }
            *(float2*)&Cp[(size_t)mr * Dd + nc]       = make_float2(v0, v1);
            *(float2*)&Cp[(size_t)(mr + 8) * Dd + nc] = make_float2(v2, v3);
        }
    }
}

// =====================================================================
// Kernel A: token mixing (R9 version: TOK=4, 256 thr, 2 CTAs/SM)
// =====================================================================
#define KA_SMEM ((4*2048 + 8*4*160 + 4*160 + 4*64) * 4)   // 56832 B

__global__ void __launch_bounds__(256) kA(
    const float* __restrict__ x,   const float* __restrict__ shift,
    const float* __restrict__ tmx, const float* __restrict__ tmw,
    const float* __restrict__ tmk, const float* __restrict__ tmv,
    const float* __restrict__ tmr, const float* __restrict__ tmg,
    const float* __restrict__ w1,  const float* __restrict__ w2,
    const float* __restrict__ td,  const float* __restrict__ dw1,
    const float* __restrict__ dw2)
{
    extern __shared__ float sm[];
    float* sxxx = sm;                       // 4*2048
    float* ps   = sm + 4 * 2048;            // 8*4*160
    float* sst  = ps + 8 * 4 * 160;         // 4*160
    float* ssh  = sst + 4 * 160;            // 4*64

    const int tid  = threadIdx.x;
    const int wqid = tid >> 5;
    const int lane = tid & 31;
    const int t0   = blockIdx.x * TOK;

    for (int tok = 0; tok < TOK; tok++) {
        int gt = t0 + tok;
        int b = gt / Tt, tt = gt % Tt;
        const float* xrow = x + (size_t)gt * Dd;
        const float* xprv = (tt == 0) ? (shift + (size_t)b * Dd)
                                      : (x + (size_t)(gt - 1) * Dd);
        for (int d = tid; d < Dd; d += 256) {
            float xv_ = xrow[d];
            sxxx[tok * Dd + d] = xv_ + (xprv[d] - xv_) * tmx[d];
        }
    }
    __syncthreads();

    {
        float acc[5][TOK];
        #pragma unroll
        for (int g = 0; g < 5; g++)
            #pragma unroll
            for (int t = 0; t < TOK; t++) acc[g][t] = 0.f;
        const int d0 = wqid * 256;
        for (int dd = 0; dd < 256; dd++) {
            int d = d0 + dd;
            float xv[TOK];
            #pragma unroll
            for (int t = 0; t < TOK; t++) xv[t] = sxxx[t * Dd + d];
            #pragma unroll
            for (int g = 0; g < 5; g++) {
                float w1v = w1[d * 160 + g * 32 + lane];
                #pragma unroll
                for (int t = 0; t < TOK; t++) acc[g][t] += xv[t] * w1v;
            }
        }
        #pragma unroll
        for (int g = 0; g < 5; g++)
            #pragma unroll
            for (int t = 0; t < TOK; t++)
                ps[(wqid * TOK + t) * 160 + g * 32 + lane] = acc[g][t];
        __syncthreads();
        for (int idx = tid; idx < TOK * 160; idx += 256) {
            int t = idx / 160, j = idx % 160;
            float s = 0.f;
            #pragma unroll
            for (int w8 = 0; w8 < 8; w8++) s += ps[(w8 * TOK + t) * 160 + j];
            sst[t * 160 + j] = tanhf(s);
        }
        __syncthreads();
    }

    for (int d = tid; d < Dd; d += 256) {
        float macc[TOK][5];
        #pragma unroll
        for (int t = 0; t < TOK; t++)
            #pragma unroll
            for (int g = 0; g < 5; g++) macc[t][g] = 0.f;

        #pragma unroll
        for (int g = 0; g < 5; g++) {
            for (int j32 = 0; j32 < 32; j32++) {
                int j = g * 32 + j32;
                float w2v = w2[(size_t)j * Dd + d];
                #pragma unroll
                for (int t = 0; t < TOK; t++) macc[t][g] += sst[t * 160 + j] * w2v;
            }
        }
        float twv = tmw[d], tkv = tmk[d], tvv = tmv[d], trv = tmr[d], tgv = tmg[d];
        #pragma unroll
        for (int tok = 0; tok < TOK; tok++) {
            int gt = t0 + tok;
            int b = gt / Tt, tt = gt % Tt;
            float xv_ = x[(size_t)gt * Dd + d];
            float xpv = (tt == 0) ? shift[(size_t)b * Dd + d]
                                  : x[(size_t)(gt - 1) * Dd + d];
            float dx = xpv - xv_;
            size_t o = (size_t)gt * Dd + d;
            split_fp16(xv_ + dx * (tkv + macc[tok][1]), g_xkh[o], g_xkl[o]);
            split_fp16(xv_ + dx * (tvv + macc[tok][2]), g_xvh[o], g_xvl[o]);
            split_fp16(xv_ + dx * (trv + macc[tok][3]), g_xrh[o], g_xrl[o]);
            split_fp16(xv_ + dx * (tgv + macc[tok][4]), g_xgh[o], g_xgl[o]);
            sxxx[tok * Dd + d] = xv_ + dx * (twv + macc[tok][0]);
        }
    }
    __syncthreads();

    {
        float acc[2][TOK];
        #pragma unroll
        for (int g = 0; g < 2; g++)
            #pragma unroll
            for (int t = 0; t < TOK; t++) acc[g][t] = 0.f;
        const int d0 = wqid * 256;
        for (int dd = 0; dd < 256; dd++) {
            int d = d0 + dd;
            float xv[TOK];
            #pragma unroll
            for (int t = 0; t < TOK; t++) xv[t] = sxxx[t * Dd + d];
            #pragma unroll
            for (int g = 0; g < 2; g++) {
                float w1v = dw1[d * 64 + g * 32 + lane];
                #pragma unroll
                for (int t = 0; t < TOK; t++) acc[g][t] += xv[t] * w1v;
            }
        }
        #pragma unroll
        for (int g = 0; g < 2; g++)
            #pragma unroll
            for (int t = 0; t < TOK; t++)
                ps[(wqid * TOK + t) * 64 + g * 32 + lane] = acc[g][t];
        __syncthreads();
        for (int idx = tid; idx < TOK * 64; idx += 256) {
            int t = idx / 64, j = idx % 64;
            float s = 0.f;
            #pragma unroll
            for (int w8 = 0; w8 < 8; w8++) s += ps[(w8 * TOK + t) * 64 + j];
            ssh[t * 64 + j] = tanhf(s);
        }
        __syncthreads();
    }

    for (int d = tid; d < Dd; d += 256) {
        float acc[TOK];
        #pragma unroll
        for (int t = 0; t < TOK; t++) acc[t] = 0.f;
        for (int j = 0; j < 64; j++) {
            float w2v = dw2[(size_t)j * Dd + d];
            #pragma unroll
            for (int t = 0; t < TOK; t++) acc[t] += ssh[t * 64 + j] * w2v;
        }
        float tdv = td[d];
        #pragma unroll
        for (int t = 0; t < TOK; t++) {
            float wdv = fmaxf(expf(-expf(tdv + acc[t])), 0.005f);
            g_wd[(size_t)(t0 + t) * Dd + d] = wdv;
        }
    }
}

// =====================================================================
// Weight convert: fp32 -> fp16
// =====================================================================
struct ConvArgs {
    const float* s[5];
    __half* h[5];
};

__global__ void __launch_bounds__(256) wconv_all(ConvArgs ca)
{
    const int z = blockIdx.y;
    const float* src = ca.s[z];
    __half* hi = ca.h[z];
    int i = (blockIdx.x * 256 + threadIdx.x) * 4;
    float4 v = *(const float4*)(src + i);
    __half2* hp = (__half2*)(hi + i);
    hp[0] = __floats2half2_rn(v.x, v.y);
    hp[1] = __floats2half2_rn(v.z, v.w);
}

// =====================================================================
// WKV pass 1 (CH=128, double-buffered smem, 1 sync/step, prefetch)
// =====================================================================
__global__ void __launch_bounds__(64) wkv_pass1(
    const float* __restrict__ kbuf, const float* __restrict__ vbuf)
{
    const int cid = blockIdx.x;
    const int n  = cid % NCH;
    const int bh = cid / NCH;
    const int h  = bh % Hh;
    const int b  = bh / Hh;
    const int j  = threadIdx.x;

    __shared__ float2 sp[2][64];
    float S[64];
    #pragma unroll
    for (int k = 0; k < 64; k++) S[k] = 0.f;
    float wsa = 1.f;

    size_t base = ((size_t)(b * Tt + n * CH)) * Dd + h * 64 + j;
    float kk = kbuf[base];
    float wd = g_wd[base];
    float vj = vbuf[base];

    for (int tt = 0; tt < CH; tt++) {
        const int buf = tt & 1;
        sp[buf][j] = make_float2(kk, wd);
        wsa *= wd;
        __syncthreads();
        if (tt + 1 < CH) {
            size_t o = base + (size_t)(tt + 1) * Dd;
            kk = kbuf[o];
            wd = g_wd[o];
        }
        float vc = vj;
        if (tt + 1 < CH) vj = vbuf[base + (size_t)(tt + 1) * Dd];
        const float4* p4 = (const float4*)sp[buf];
        #pragma unroll
        for (int kq = 0; kq < 32; kq++) {
            float4 q = p4[kq];
            S[2 * kq]     = q.y * S[2 * kq]     + q.x * vc;
            S[2 * kq + 1] = q.w * S[2 * kq + 1] + q.z * vc;
        }
    }
    float* cs = g_cs + (size_t)cid * 4096;
    #pragma unroll
    for (int k = 0; k < 64; k++) cs[k * 64 + j] = S[k];
    g_ws[cid * 64 + j] = wsa;
}

// =====================================================================
// WKV pass 2: scan over chunks
// =====================================================================
__global__ void __launch_bounds__(64) wkv_pass2(
    const float* __restrict__ state0, float* __restrict__ out_state)
{
    const int bh = blockIdx.x;
    const int j  = threadIdx.x;
    __shared__ float sws[64];

    float S[64];
    const float* s0 = state0 + (size_t)bh * 4096;
    #pragma unroll
    for (int k = 0; k < 64; k++) S[k] = s0[k * 64 + j];

    for (int n = 0; n < NCH; n++) {
        size_t cid = (size_t)bh * NCH + n;
        float* es = g_es + cid * 4096;
        #pragma unroll
        for (int k = 0; k < 64; k++) es[k * 64 + j] = S[k];
        sws[j] = g_ws[cid * 64 + j];
        __syncthreads();
        const float* cs = g_cs + cid * 4096;
        #pragma unroll
        for (int k = 0; k < 64; k++)
            S[k] = S[k] * sws[k] + cs[k * 64 + j];
        __syncthreads();
    }
    float* os = out_state + (size_t)bh * 4096;
    #pragma unroll
    for (int k = 0; k < 64; k++) os[k * 64 + j] = S[k];
}

// =====================================================================
// WKV pass 3 FUSED with GroupNorm * silu-gate -> writes yh/yl directly.
// At each step the CTA's 64 threads hold one head's 64 channels for one
// token == one GroupNorm group. Cross-warp reduce for mean/var.
// =====================================================================
__global__ void __launch_bounds__(64) wkv_pass3(
    const float* __restrict__ rbuf, const float* __restrict__ kbuf,
    const float* __restrict__ vbuf, const float* __restrict__ faaaa,
    const float* __restrict__ gamma, const float* __restrict__ beta)
{
    const int cid = blockIdx.x;
    const int n  = cid % NCH;
    const int bh = cid / NCH;
    const int h  = bh % Hh;
    const int b  = bh / Hh;
    const int j  = threadIdx.x;
    const int wq = j >> 5;      // 0/1
    const int lane = j & 31;

    __shared__ float4 sq[2][64];
    __shared__ float2 sred[2];

    float S[64];
    const float* es = g_es + (size_t)cid * 4096;
    #pragma unroll
    for (int k = 0; k < 64; k++) S[k] = es[k * 64 + j];
    const float uj  = faaaa[h * 64 + j];
    const float gam = gamma[h * 64 + j];
    const float bet = beta [h * 64 + j];

    size_t base = ((size_t)(b * Tt + n * CH)) * Dd + h * 64 + j;
    float kk = kbuf[base];
    float wd = g_wd[base];
    float rr = rbuf[base];
    float vj = vbuf[base];
    float gg = g_g[base];

    for (int tt = 0; tt < CH; tt++) {
        const int buf = tt & 1;
        sq[buf][j] = make_float4(kk, wd, rr, rr * uj * kk);
        __syncthreads();
        size_t ocur = base + (size_t)tt * Dd;
        float vc = vj, gc = gg;
        if (tt + 1 < CH) {
            size_t o = ocur + Dd;
            kk = kbuf[o];
            wd = g_wd[o];
            rr = rbuf[o];
            vj = vbuf[o];
            gg = g_g[o];
        }
        float outv = 0.f, rk = 0.f;
        const float4* qb = sq[buf];
        #pragma unroll
        for (int k = 0; k < 64; k++) {
            float4 q = qb[k];
            outv += q.z * S[k];
            rk   += q.w;
            S[k] = q.y * S[k] + q.x * vc;
        }
        float y = outv + rk * vc;

        // GroupNorm over the 64 threads (one head, one token)
        float s1 = y, s2 = y * y;
        #pragma unroll
        for (int off = 16; off > 0; off >>= 1) {
            s1 += __shfl_xor_sync(0xffffffffu, s1, off);
            s2 += __shfl_xor_sync(0xffffffffu, s2, off);
        }
        if (lane == 0) sred[wq] = make_float2(s1, s2);
        __syncthreads();
        float ts1 = sred[0].x + sred[1].x;
        float ts2 = sred[0].y + sred[1].y;
        float mu  = ts1 * (1.f / 64.f);
        float var = ts2 * (1.f / 64.f) - mu * mu;
        float inv = rsqrtf(var + EPSV);
        float yo  = ((y - mu) * inv * gam + bet) * gc;
        split_fp16(yo, g_yh[ocur], g_yl[ocur]);
    }
}

__global__ void __launch_bounds__(256) xlast_copy(
    const float* __restrict__ x, float* __restrict__ dst)
{
    int i = blockIdx.x * 256 + threadIdx.x;
    int b = i / Dd, d = i % Dd;
    dst[i] = x[((size_t)b * Tt + Tt - 1) * Dd + d];
}

// =====================================================================
// launch — two-stream schedule (R13) with fused pass3
// =====================================================================
extern "C" void kernel_launch(void* const* d_in, const int* in_sizes, int n_in,
                              void* d_out, int out_size)
{
    const float* x      = (const float*)d_in[0];
    const float* shift  = (const float*)d_in[1];
    const float* state0 = (const float*)d_in[2];
    const float* tmx    = (const float*)d_in[3];
    const float* tmw    = (const float*)d_in[4];
    const float* tmk    = (const float*)d_in[5];
    const float* tmv    = (const float*)d_in[6];
    const float* tmr    = (const float*)d_in[7];
    const float* tmg    = (const float*)d_in[8];
    const float* w1     = (const float*)d_in[9];
    const float* w2     = (const float*)d_in[10];
    const float* td     = (const float*)d_in[11];
    const float* dw1    = (const float*)d_in[12];
    const float* dw2    = (const float*)d_in[13];
    const float* faaaa  = (const float*)d_in[14];
    const float* Wr     = (const float*)d_in[15];
    const float* Wk     = (const float*)d_in[16];
    const float* Wv     = (const float*)d_in[17];
    const float* Wg     = (const float*)d_in[18];
    const float* Wo     = (const float*)d_in[19];
    const float* gamma  = (const float*)d_in[20];
    const float* beta   = (const float*)d_in[21];
    float* out = (float*)d_out;

    __half *xkh,*xkl,*xvh,*xvl,*xrh,*xrl,*xgh,*xgl,*yh,*yl;
    __half *Wrh,*Wkh,*Wvh,*Wgh,*Woh;
    float *rb,*kb,*vb,*gb;
    cudaGetSymbolAddress((void**)&xkh, g_xkh); cudaGetSymbolAddress((void**)&xkl, g_xkl);
    cudaGetSymbolAddress((void**)&xvh, g_xvh); cudaGetSymbolAddress((void**)&xvl, g_xvl);
    cudaGetSymbolAddress((void**)&xrh, g_xrh); cudaGetSymbolAddress((void**)&xrl, g_xrl);
    cudaGetSymbolAddress((void**)&xgh, g_xgh); cudaGetSymbolAddress((void**)&xgl, g_xgl);
    cudaGetSymbolAddress((void**)&yh,  g_yh);  cudaGetSymbolAddress((void**)&yl,  g_yl);
    cudaGetSymbolAddress((void**)&Wrh, g_Wrh);
    cudaGetSymbolAddress((void**)&Wkh, g_Wkh);
    cudaGetSymbolAddress((void**)&Wvh, g_Wvh);
    cudaGetSymbolAddress((void**)&Wgh, g_Wgh);
    cudaGetSymbolAddress((void**)&Woh, g_Woh);
    cudaGetSymbolAddress((void**)&rb, g_r);
    cudaGetSymbolAddress((void**)&kb, g_k);
    cudaGetSymbolAddress((void**)&vb, g_v);
    cudaGetSymbolAddress((void**)&gb, g_g);

    const size_t BTD = (size_t)BT * Dd;

    static cudaStream_t s2 = nullptr;
    static cudaEvent_t eFork = nullptr, eW = nullptr, eKV = nullptr, eRG = nullptr;
    if (!s2) {
        cudaStreamCreateWithFlags(&s2, cudaStreamNonBlocking);
        cudaEventCreateWithFlags(&eFork, cudaEventDisableTiming);
        cudaEventCreateWithFlags(&eW,    cudaEventDisableTiming);
        cudaEventCreateWithFlags(&eKV,   cudaEventDisableTiming);
        cudaEventCreateWithFlags(&eRG,   cudaEventDisableTiming);
        cudaFuncSetAttribute(gemm4, cudaFuncAttributeMaxDynamicSharedMemorySize, G_SMEM);
        cudaFuncSetAttribute(kA,    cudaFuncAttributeMaxDynamicSharedMemorySize, KA_SMEM);
    }

    // ---- fork: s2 does weight convert + xlast while s0 does kA ----
    cudaEventRecord(eFork, 0);
    cudaStreamWaitEvent(s2, eFork, 0);

    ConvArgs ca;
    ca.s[0] = Wr; ca.h[0] = Wrh;
    ca.s[1] = Wk; ca.h[1] = Wkh;
    ca.s[2] = Wv; ca.h[2] = Wvh;
    ca.s[3] = Wg; ca.h[3] = Wgh;
    ca.s[4] = Wo; ca.h[4] = Woh;
    dim3 wsg((Dd * Dd) / (256 * 4), 5);
    wconv_all<<<wsg, 256, 0, s2>>>(ca);
    xlast_copy<<<(Bb * Dd) / 256, 256, 0, s2>>>(x, out + BTD);

    kA<<<BT / TOK, 256, KA_SMEM, 0>>>(x, shift, tmx, tmw, tmk, tmv, tmr, tmg,
                                      w1, w2, td, dw1, dw2);

    cudaEventRecord(eW, s2);
    cudaStreamWaitEvent(0, eW, 0);

    // ---- gemm(k, v) on s0 ----
    GemmArgs gkv;
    gkv.Ah[0] = xkh; gkv.Al[0] = xkl; gkv.Wh[0] = Wkh; gkv.C[0] = kb; gkv.mode[0] = 0;
    gkv.Ah[1] = xvh; gkv.Al[1] = xvl; gkv.Wh[1] = Wvh; gkv.C[1] = vb; gkv.mode[1] = 0;
    dim3 gg2(Dd / 128, BT / 128, 2);
    gemm4<<<gg2, 256, G_SMEM, 0>>>(gkv);

    // fork: s2 runs gemm(r, g) concurrent with pass1/pass2 on s0
    cudaEventRecord(eKV, 0);
    cudaStreamWaitEvent(s2, eKV, 0);

    GemmArgs grg;
    grg.Ah[0] = xrh; grg.Al[0] = xrl; grg.Wh[0] = Wrh; grg.C[0] = rb; grg.mode[0] = 0;
    grg.Ah[1] = xgh; grg.Al[1] = xgl; grg.Wh[1] = Wgh; grg.C[1] = gb; grg.mode[1] = 1;
    gemm4<<<gg2, 256, G_SMEM, s2>>>(grg);

    wkv_pass1<<<Bb * Hh * NCH, 64, 0, 0>>>(kb, vb);
    wkv_pass2<<<Bb * Hh, 64, 0, 0>>>(state0, out + BTD + (size_t)Bb * Dd);

    // join r/g before fused pass3
    cudaEventRecord(eRG, s2);
    cudaStreamWaitEvent(0, eRG, 0);

    wkv_pass3<<<Bb * Hh * NCH, 64, 0, 0>>>(rb, kb, vb, faaaa, gamma, beta);

    GemmArgs go_;
    go_.Ah[0] = yh; go_.Al[0] = yl; go_.Wh[0] = Woh; go_.C[0] = out; go_.mode[0] = 0;
    dim3 go(Dd / 128, BT / 128, 1);
    gemm4<<<go, 256, G_SMEM, 0>>>(go_);
}

// round 15
// speedup vs baseline: 1.0142x; 1.0142x over previous
#include <cuda_runtime.h>
#include <cuda_fp16.h>
#include <math.h>
#include <stdint.h>

// ---------------- problem constants ----------------
#define Bb   2
#define Tt   2048
#define Dd   2048
#define Hh   32
#define Kd   64
#define CH   128
#define NCH  (Tt / CH)          // 16
#define BT   (Bb * Tt)          // 4096
#define TOK  4
#define EPSV 6.4e-4f

// ---------------- scratch (device globals, no cudaMalloc) ----------------
__device__ __half g_xkh[BT * Dd], g_xkl[BT * Dd];
__device__ __half g_xvh[BT * Dd], g_xvl[BT * Dd];
__device__ __half g_xrh[BT * Dd], g_xrl[BT * Dd];
__device__ __half g_xgh[BT * Dd], g_xgl[BT * Dd];
__device__ __half g_yh [BT * Dd], g_yl [BT * Dd];
__device__ __half g_Wrh[Dd * Dd];
__device__ __half g_Wkh[Dd * Dd];
__device__ __half g_Wvh[Dd * Dd];
__device__ __half g_Wgh[Dd * Dd];
__device__ __half g_Woh[Dd * Dd];
__device__ float g_wd[BT * Dd];
__device__ float g_r [BT * Dd];
__device__ float g_k [BT * Dd];
__device__ float g_v [BT * Dd];
__device__ float g_g [BT * Dd];
__device__ float g_cs[Bb * Hh * NCH * Kd * Kd];
__device__ float g_es[Bb * Hh * NCH * Kd * Kd];
__device__ float g_ws[Bb * Hh * NCH * Kd];

__device__ __forceinline__ void split_fp16(float v, __half& h, __half& l) {
    h = __float2half_rn(v);
    l = __float2half_rn(v - __half2float(h));
}

// ---------------- PTX helpers ----------------
#define LDSM4(r0,r1,r2,r3,addr) \
    asm volatile("ldmatrix.sync.aligned.m8n8.x4.shared.b16 {%0,%1,%2,%3}, [%4];" \
        : "=r"(r0),"=r"(r1),"=r"(r2),"=r"(r3) : "r"(addr))

#define MMA16816F(d,a,b) \
    asm volatile("mma.sync.aligned.m16n8k16.row.col.f32.f16.f16.f32 " \
        "{%0,%1,%2,%3},{%4,%5,%6,%7},{%8,%9},{%0,%1,%2,%3};" \
        : "+f"(d[0]),"+f"(d[1]),"+f"(d[2]),"+f"(d[3]) \
        : "r"(a[0]),"r"(a[1]),"r"(a[2]),"r"(a[3]),"r"(b[0]),"r"(b[1]))

#define CP_ASYNC16(dst, src) \
    asm volatile("cp.async.cg.shared.global [%0], [%1], 16;" :: "r"(dst), "l"(src) : "memory")
#define CP_COMMIT() asm volatile("cp.async.commit_group;" ::: "memory")
#define CP_WAIT1()  asm volatile("cp.async.wait_group 1;" ::: "memory")

// =====================================================================
// Batched tensor-core GEMM (mma.sync), fp16 split: C = Ah.Wh [+ Al.Wh]
// nit[z]=64 -> 2-pass (A exact); nit[z]=32 -> 1-pass (A fp16-rounded).
// 128x128 CTA tile, BK=64, 3-stage cp.async pipeline, 8 warps.
// =====================================================================
#define G_STAGE 32768
#define G_SMEM  (3 * G_STAGE)

struct GemmArgs {
    const __half* Ah[4];
    const __half* Al[4];
    const __half* Wh[4];
    float* C[4];
    int mode[4];
    int nit[4];
};

__device__ __forceinline__ void issue_chunk(
    int nx, uint32_t sbase, int m0, int n0, int tid,
    const __half* Ah, const __half* Al, const __half* Wh)
{
    const int pass = nx >> 5;
    const int kk   = (nx & 31) << 6;
    const __half* Ap = pass ? Al : Ah;
    uint32_t sa = sbase + (nx % 3) * G_STAGE;
    uint32_t sb = sa + 16384;
    #pragma unroll
    for (int i = 0; i < 4; i++) {
        int ch = tid + i * 256;
        int r = ch >> 3, c = ch & 7;
        uint32_t soff = r * 128 + ((c ^ (r & 7)) << 4);
        CP_ASYNC16(sa + soff, Ap + (size_t)(m0 + r) * Dd + kk + c * 8);
        CP_ASYNC16(sb + soff, Wh + (size_t)(n0 + r) * Dd + kk + c * 8);
    }
}

__global__ void __launch_bounds__(256) gemm4(GemmArgs ga)
{
    extern __shared__ char gsm[];
    uint32_t sbase;
    asm("{ .reg .u64 t; cvta.to.shared.u64 t, %1; cvt.u32.u64 %0, t; }"
        : "=r"(sbase) : "l"(gsm));

    const int z = blockIdx.z;
    const __half* Ahp = ga.Ah[z];
    const __half* Alp = ga.Al[z];
    const __half* Whp = ga.Wh[z];
    float* Cp = ga.C[z];
    const int mode = ga.mode[z];
    const int NIT  = ga.nit[z];

    const int tid  = threadIdx.x;
    const int lane = tid & 31;
    const int w    = tid >> 5;
    const int wm   = w >> 2;
    const int wn   = w & 3;
    const int m0   = blockIdx.y * 128;
    const int n0   = blockIdx.x * 128;

    const int rlo = (lane & 7) + ((lane >> 3) & 1) * 8;
    const int lg  = lane >> 4;

    int arow[4], asw[4];
    #pragma unroll
    for (int i = 0; i < 4; i++) {
        int r = wm * 64 + i * 16 + rlo;
        arow[i] = r * 128;
        asw[i]  = r & 7;
    }
    int brow[2], bsw[2];
    #pragma unroll
    for (int jp = 0; jp < 2; jp++) {
        int r = wn * 32 + jp * 16 + rlo;
        brow[jp] = r * 128;
        bsw[jp]  = r & 7;
    }

    float acc[4][4][4];
    #pragma unroll
    for (int i = 0; i < 4; i++)
        #pragma unroll
        for (int j = 0; j < 4; j++)
            #pragma unroll
            for (int q = 0; q < 4; q++) acc[i][j][q] = 0.f;

    issue_chunk(0, sbase, m0, n0, tid, Ahp, Alp, Whp); CP_COMMIT();
    issue_chunk(1, sbase, m0, n0, tid, Ahp, Alp, Whp); CP_COMMIT();

    for (int it = 0; it < NIT; it++) {
        CP_WAIT1();
        __syncthreads();

        if (it + 2 < NIT)
            issue_chunk(it + 2, sbase, m0, n0, tid, Ahp, Alp, Whp);
        CP_COMMIT();

        uint32_t abase = sbase + (it % 3) * G_STAGE;
        uint32_t bbase = abase + 16384;
        #pragma unroll
        for (int ks = 0; ks < 4; ks++) {
            const int cc = ks * 2 + lg;
            uint32_t a[4][4], b[4][2];
            #pragma unroll
            for (int i = 0; i < 4; i++) {
                uint32_t addr = abase + arow[i] + ((cc ^ asw[i]) << 4);
                LDSM4(a[i][0], a[i][1], a[i][2], a[i][3], addr);
            }
            #pragma unroll
            for (int jp = 0; jp < 2; jp++) {
                uint32_t addr = bbase + brow[jp] + ((cc ^ bsw[jp]) << 4);
                uint32_t t0, t1, t2, t3;
                LDSM4(t0, t1, t2, t3, addr);
                b[2 * jp][0] = t0; b[2 * jp + 1][0] = t1;
                b[2 * jp][1] = t2; b[2 * jp + 1][1] = t3;
            }
            #pragma unroll
            for (int i = 0; i < 4; i++)
                #pragma unroll
                for (int j = 0; j < 4; j++)
                    MMA16816F(acc[i][j], a[i], b[j]);
        }
    }

    #pragma unroll
    for (int i = 0; i < 4; i++) {
        int mr = m0 + wm * 64 + i * 16 + (lane >> 2);
        #pragma unroll
        for (int j = 0; j < 4; j++) {
            int nc = n0 + wn * 32 + j * 8 + (lane & 3) * 2;
            float v0 = acc[i][j][0], v1 = acc[i][j][1];
            float v2 = acc[i][j][2], v3 = acc[i][j][3];
            if (mode == 1) {
                v0 = v0 / (1.f + expf(-v0));
                v1 = v1 / (1.f + expf(-v1));
                v2 = v2 / (1.f + expf(-v2));
                v3 = v3 / (1.f + expf(-v3));
            }
            *(float2*)&Cp[(size_t)mr * Dd + nc]       = make_float2(v0, v1);
            *(float2*)&Cp[(size_t)(mr + 8) * Dd + nc] = make_float2(v2, v3);
        }
    }
}

// =====================================================================
// Kernel A: token mixing (R9 version: TOK=4, 256 thr, 2 CTAs/SM)
// =====================================================================
#define KA_SMEM ((4*2048 + 8*4*160 + 4*160 + 4*64) * 4)   // 56832 B

__global__ void __launch_bounds__(256) kA(
    const float* __restrict__ x,   const float* __restrict__ shift,
    const float* __restrict__ tmx, const float* __restrict__ tmw,
    const float* __restrict__ tmk, const float* __restrict__ tmv,
    const float* __restrict__ tmr, const float* __restrict__ tmg,
    const float* __restrict__ w1,  const float* __restrict__ w2,
    const float* __restrict__ td,  const float* __restrict__ dw1,
    const float* __restrict__ dw2)
{
    extern __shared__ float sm[];
    float* sxxx = sm;                       // 4*2048
    float* ps   = sm + 4 * 2048;            // 8*4*160
    float* sst  = ps + 8 * 4 * 160;         // 4*160
    float* ssh  = sst + 4 * 160;            // 4*64

    const int tid  = threadIdx.x;
    const int wqid = tid >> 5;
    const int lane = tid & 31;
    const int t0   = blockIdx.x * TOK;

    for (int tok = 0; tok < TOK; tok++) {
        int gt = t0 + tok;
        int b = gt / Tt, tt = gt % Tt;
        const float* xrow = x + (size_t)gt * Dd;
        const float* xprv = (tt == 0) ? (shift + (size_t)b * Dd)
                                      : (x + (size_t)(gt - 1) * Dd);
        for (int d = tid; d < Dd; d += 256) {
            float xv_ = xrow[d];
            sxxx[tok * Dd + d] = xv_ + (xprv[d] - xv_) * tmx[d];
        }
    }
    __syncthreads();

    {
        float acc[5][TOK];
        #pragma unroll
        for (int g = 0; g < 5; g++)
            #pragma unroll
            for (int t = 0; t < TOK; t++) acc[g][t] = 0.f;
        const int d0 = wqid * 256;
        for (int dd = 0; dd < 256; dd++) {
            int d = d0 + dd;
            float xv[TOK];
            #pragma unroll
            for (int t = 0; t < TOK; t++) xv[t] = sxxx[t * Dd + d];
            #pragma unroll
            for (int g = 0; g < 5; g++) {
                float w1v = w1[d * 160 + g * 32 + lane];
                #pragma unroll
                for (int t = 0; t < TOK; t++) acc[g][t] += xv[t] * w1v;
            }
        }
        #pragma unroll
        for (int g = 0; g < 5; g++)
            #pragma unroll
            for (int t = 0; t < TOK; t++)
                ps[(wqid * TOK + t) * 160 + g * 32 + lane] = acc[g][t];
        __syncthreads();
        for (int idx = tid; idx < TOK * 160; idx += 256) {
            int t = idx / 160, j = idx % 160;
            float s = 0.f;
            #pragma unroll
            for (int w8 = 0; w8 < 8; w8++) s += ps[(w8 * TOK + t) * 160 + j];
            sst[t * 160 + j] = tanhf(s);
        }
        __syncthreads();
    }

    for (int d = tid; d < Dd; d += 256) {
        float macc[TOK][5];
        #pragma unroll
        for (int t = 0; t < TOK; t++)
            #pragma unroll
            for (int g = 0; g < 5; g++) macc[t][g] = 0.f;

        #pragma unroll
        for (int g = 0; g < 5; g++) {
            for (int j32 = 0; j32 < 32; j32++) {
                int j = g * 32 + j32;
                float w2v = w2[(size_t)j * Dd + d];
                #pragma unroll
                for (int t = 0; t < TOK; t++) macc[t][g] += sst[t * 160 + j] * w2v;
            }
        }
        float twv = tmw[d], tkv = tmk[d], tvv = tmv[d], trv = tmr[d], tgv = tmg[d];
        #pragma unroll
        for (int tok = 0; tok < TOK; tok++) {
            int gt = t0 + tok;
            int b = gt / Tt, tt = gt % Tt;
            float xv_ = x[(size_t)gt * Dd + d];
            float xpv = (tt == 0) ? shift[(size_t)b * Dd + d]
                                  : x[(size_t)(gt - 1) * Dd + d];
            float dx = xpv - xv_;
            size_t o = (size_t)gt * Dd + d;
            split_fp16(xv_ + dx * (tkv + macc[tok][1]), g_xkh[o], g_xkl[o]);
            split_fp16(xv_ + dx * (tvv + macc[tok][2]), g_xvh[o], g_xvl[o]);
            split_fp16(xv_ + dx * (trv + macc[tok][3]), g_xrh[o], g_xrl[o]);
            split_fp16(xv_ + dx * (tgv + macc[tok][4]), g_xgh[o], g_xgl[o]);
            sxxx[tok * Dd + d] = xv_ + dx * (twv + macc[tok][0]);
        }
    }
    __syncthreads();

    {
        float acc[2][TOK];
        #pragma unroll
        for (int g = 0; g < 2; g++)
            #pragma unroll
            for (int t = 0; t < TOK; t++) acc[g][t] = 0.f;
        const int d0 = wqid * 256;
        for (int dd = 0; dd < 256; dd++) {
            int d = d0 + dd;
            float xv[TOK];
            #pragma unroll
            for (int t = 0; t < TOK; t++) xv[t] = sxxx[t * Dd + d];
            #pragma unroll
            for (int g = 0; g < 2; g++) {
                float w1v = dw1[d * 64 + g * 32 + lane];
                #pragma unroll
                for (int t = 0; t < TOK; t++) acc[g][t] += xv[t] * w1v;
            }
        }
        #pragma unroll
        for (int g = 0; g < 2; g++)
            #pragma unroll
            for (int t = 0; t < TOK; t++)
                ps[(wqid * TOK + t) * 64 + g * 32 + lane] = acc[g][t];
        __syncthreads();
        for (int idx = tid; idx < TOK * 64; idx += 256) {
            int t = idx / 64, j = idx % 64;
            float s = 0.f;
            #pragma unroll
            for (int w8 = 0; w8 < 8; w8++) s += ps[(w8 * TOK + t) * 64 + j];
            ssh[t * 64 + j] = tanhf(s);
        }
        __syncthreads();
    }

    for (int d = tid; d < Dd; d += 256) {
        float acc[TOK];
        #pragma unroll
        for (int t = 0; t < TOK; t++) acc[t] = 0.f;
        for (int j = 0; j < 64; j++) {
            float w2v = dw2[(size_t)j * Dd + d];
            #pragma unroll
            for (int t = 0; t < TOK; t++) acc[t] += ssh[t * 64 + j] * w2v;
        }
        float tdv = td[d];
        #pragma unroll
        for (int t = 0; t < TOK; t++) {
            float wdv = fmaxf(expf(-expf(tdv + acc[t])), 0.005f);
            g_wd[(size_t)(t0 + t) * Dd + d] = wdv;
        }
    }
}

// =====================================================================
// Weight convert: fp32 -> fp16
// =====================================================================
struct ConvArgs {
    const float* s[5];
    __half* h[5];
};

__global__ void __launch_bounds__(256) wconv_all(ConvArgs ca)
{
    const int z = blockIdx.y;
    const float* src = ca.s[z];
    __half* hi = ca.h[z];
    int i = (blockIdx.x * 256 + threadIdx.x) * 4;
    float4 v = *(const float4*)(src + i);
    __half2* hp = (__half2*)(hi + i);
    hp[0] = __floats2half2_rn(v.x, v.y);
    hp[1] = __floats2half2_rn(v.z, v.w);
}

// =====================================================================
// WKV pass 1 (CH=128, double-buffered smem, 1 sync/step, prefetch)
// =====================================================================
__global__ void __launch_bounds__(64) wkv_pass1(
    const float* __restrict__ kbuf, const float* __restrict__ vbuf)
{
    const int cid = blockIdx.x;
    const int n  = cid % NCH;
    const int bh = cid / NCH;
    const int h  = bh % Hh;
    const int b  = bh / Hh;
    const int j  = threadIdx.x;

    __shared__ float2 sp[2][64];
    float S[64];
    #pragma unroll
    for (int k = 0; k < 64; k++) S[k] = 0.f;
    float wsa = 1.f;

    size_t base = ((size_t)(b * Tt + n * CH)) * Dd + h * 64 + j;
    float kk = kbuf[base];
    float wd = g_wd[base];
    float vj = vbuf[base];

    for (int tt = 0; tt < CH; tt++) {
        const int buf = tt & 1;
        sp[buf][j] = make_float2(kk, wd);
        wsa *= wd;
        __syncthreads();
        if (tt + 1 < CH) {
            size_t o = base + (size_t)(tt + 1) * Dd;
            kk = kbuf[o];
            wd = g_wd[o];
        }
        float vc = vj;
        if (tt + 1 < CH) vj = vbuf[base + (size_t)(tt + 1) * Dd];
        const float4* p4 = (const float4*)sp[buf];
        #pragma unroll
        for (int kq = 0; kq < 32; kq++) {
            float4 q = p4[kq];
            S[2 * kq]     = q.y * S[2 * kq]     + q.x * vc;
            S[2 * kq + 1] = q.w * S[2 * kq + 1] + q.z * vc;
        }
    }
    float* cs = g_cs + (size_t)cid * 4096;
    #pragma unroll
    for (int k = 0; k < 64; k++) cs[k * 64 + j] = S[k];
    g_ws[cid * 64 + j] = wsa;
}

// =====================================================================
// WKV pass 2: scan over chunks
// =====================================================================
__global__ void __launch_bounds__(64) wkv_pass2(
    const float* __restrict__ state0, float* __restrict__ out_state)
{
    const int bh = blockIdx.x;
    const int j  = threadIdx.x;
    __shared__ float sws[64];

    float S[64];
    const float* s0 = state0 + (size_t)bh * 4096;
    #pragma unroll
    for (int k = 0; k < 64; k++) S[k] = s0[k * 64 + j];

    for (int n = 0; n < NCH; n++) {
        size_t cid = (size_t)bh * NCH + n;
        float* es = g_es + cid * 4096;
        #pragma unroll
        for (int k = 0; k < 64; k++) es[k * 64 + j] = S[k];
        sws[j] = g_ws[cid * 64 + j];
        __syncthreads();
        const float* cs = g_cs + cid * 4096;
        #pragma unroll
        for (int k = 0; k < 64; k++)
            S[k] = S[k] * sws[k] + cs[k * 64 + j];
        __syncthreads();
    }
    float* os = out_state + (size_t)bh * 4096;
    #pragma unroll
    for (int k = 0; k < 64; k++) os[k * 64 + j] = S[k];
}

// =====================================================================
// WKV pass 3 FUSED with GroupNorm*gate, software-pipelined: the sync
// that publishes step t's operand quad also publishes step t-1's
// groupnorm partial sums -> 1 sync per step.
// =====================================================================
__global__ void __launch_bounds__(64) wkv_pass3(
    const float* __restrict__ rbuf, const float* __restrict__ kbuf,
    const float* __restrict__ vbuf, const float* __restrict__ faaaa,
    const float* __restrict__ gamma, const float* __restrict__ beta)
{
    const int cid = blockIdx.x;
    const int n  = cid % NCH;
    const int bh = cid / NCH;
    const int h  = bh % Hh;
    const int b  = bh / Hh;
    const int j  = threadIdx.x;
    const int wq = j >> 5;
    const int lane = j & 31;

    __shared__ float4 sq[2][64];
    __shared__ float2 sred[2][2];    // [parity][warp]

    float S[64];
    const float* es = g_es + (size_t)cid * 4096;
    #pragma unroll
    for (int k = 0; k < 64; k++) S[k] = es[k * 64 + j];
    const float uj  = faaaa[h * 64 + j];
    const float gam = gamma[h * 64 + j];
    const float bet = beta [h * 64 + j];

    size_t base = ((size_t)(b * Tt + n * CH)) * Dd + h * 64 + j;
    float kk = kbuf[base];
    float wd = g_wd[base];
    float rr = rbuf[base];
    float vj = vbuf[base];
    float gg = g_g[base];

    float py = 0.f, ps1 = 0.f, ps2 = 0.f, pg = 0.f;
    size_t pocur = 0;

    for (int tt = 0; tt < CH; tt++) {
        const int buf = tt & 1;
        sq[buf][j] = make_float4(kk, wd, rr, rr * uj * kk);
        if (tt > 0 && lane == 0) sred[buf ^ 1][wq] = make_float2(ps1, ps2);
        __syncthreads();

        // finish groupnorm of previous step
        if (tt > 0) {
            float ts1 = sred[buf ^ 1][0].x + sred[buf ^ 1][1].x;
            float ts2 = sred[buf ^ 1][0].y + sred[buf ^ 1][1].y;
            float mu  = ts1 * (1.f / 64.f);
            float var = ts2 * (1.f / 64.f) - mu * mu;
            float inv = rsqrtf(var + EPSV);
            float yo  = ((py - mu) * inv * gam + bet) * pg;
            split_fp16(yo, g_yh[pocur], g_yl[pocur]);
        }

        size_t ocur = base + (size_t)tt * Dd;
        float vc = vj, gc = gg;
        if (tt + 1 < CH) {
            size_t o = ocur + Dd;
            kk = kbuf[o];
            wd = g_wd[o];
            rr = rbuf[o];
            vj = vbuf[o];
            gg = g_g[o];
        }
        float outv = 0.f, rk = 0.f;
        const float4* qb = sq[buf];
        #pragma unroll
        for (int k = 0; k < 64; k++) {
            float4 q = qb[k];
            outv += q.z * S[k];
            rk   += q.w;
            S[k] = q.y * S[k] + q.x * vc;
        }
        float y = outv + rk * vc;

        float s1 = y, s2 = y * y;
        #pragma unroll
        for (int off = 16; off > 0; off >>= 1) {
            s1 += __shfl_xor_sync(0xffffffffu, s1, off);
            s2 += __shfl_xor_sync(0xffffffffu, s2, off);
        }
        py = y; ps1 = s1; ps2 = s2; pg = gc; pocur = ocur;
    }

    // epilogue: final step's groupnorm
    if (lane == 0) sred[(CH - 1) & 1][wq] = make_float2(ps1, ps2);
    __syncthreads();
    {
        const int pb = (CH - 1) & 1;
        float ts1 = sred[pb][0].x + sred[pb][1].x;
        float ts2 = sred[pb][0].y + sred[pb][1].y;
        float mu  = ts1 * (1.f / 64.f);
        float var = ts2 * (1.f / 64.f) - mu * mu;
        float inv = rsqrtf(var + EPSV);
        float yo  = ((py - mu) * inv * gam + bet) * pg;
        split_fp16(yo, g_yh[pocur], g_yl[pocur]);
    }
}

__global__ void __launch_bounds__(256) xlast_copy(
    const float* __restrict__ x, float* __restrict__ dst)
{
    int i = blockIdx.x * 256 + threadIdx.x;
    int b = i / Dd, d = i % Dd;
    dst[i] = x[((size_t)b * Tt + Tt - 1) * Dd + d];
}

// =====================================================================
// launch — two-stream schedule with fused pipelined pass3
// =====================================================================
extern "C" void kernel_launch(void* const* d_in, const int* in_sizes, int n_in,
                              void* d_out, int out_size)
{
    const float* x      = (const float*)d_in[0];
    const float* shift  = (const float*)d_in[1];
    const float* state0 = (const float*)d_in[2];
    const float* tmx    = (const float*)d_in[3];
    const float* tmw    = (const float*)d_in[4];
    const float* tmk    = (const float*)d_in[5];
    const float* tmv    = (const float*)d_in[6];
    const float* tmr    = (const float*)d_in[7];
    const float* tmg    = (const float*)d_in[8];
    const float* w1     = (const float*)d_in[9];
    const float* w2     = (const float*)d_in[10];
    const float* td     = (const float*)d_in[11];
    const float* dw1    = (const float*)d_in[12];
    const float* dw2    = (const float*)d_in[13];
    const float* faaaa  = (const float*)d_in[14];
    const float* Wr     = (const float*)d_in[15];
    const float* Wk     = (const float*)d_in[16];
    const float* Wv     = (const float*)d_in[17];
    const float* Wg     = (const float*)d_in[18];
    const float* Wo     = (const float*)d_in[19];
    const float* gamma  = (const float*)d_in[20];
    const float* beta   = (const float*)d_in[21];
    float* out = (float*)d_out;

    __half *xkh,*xkl,*xvh,*xvl,*xrh,*xrl,*xgh,*xgl,*yh,*yl;
    __half *Wrh,*Wkh,*Wvh,*Wgh,*Woh;
    float *rb,*kb,*vb,*gb;
    cudaGetSymbolAddress((void**)&xkh, g_xkh); cudaGetSymbolAddress((void**)&xkl, g_xkl);
    cudaGetSymbolAddress((void**)&xvh, g_xvh); cudaGetSymbolAddress((void**)&xvl, g_xvl);
    cudaGetSymbolAddress((void**)&xrh, g_xrh); cudaGetSymbolAddress((void**)&xrl, g_xrl);
    cudaGetSymbolAddress((void**)&xgh, g_xgh); cudaGetSymbolAddress((void**)&xgl, g_xgl);
    cudaGetSymbolAddress((void**)&yh,  g_yh);  cudaGetSymbolAddress((void**)&yl,  g_yl);
    cudaGetSymbolAddress((void**)&Wrh, g_Wrh);
    cudaGetSymbolAddress((void**)&Wkh, g_Wkh);
    cudaGetSymbolAddress((void**)&Wvh, g_Wvh);
    cudaGetSymbolAddress((void**)&Wgh, g_Wgh);
    cudaGetSymbolAddress((void**)&Woh, g_Woh);
    cudaGetSymbolAddress((void**)&rb, g_r);
    cudaGetSymbolAddress((void**)&kb, g_k);
    cudaGetSymbolAddress((void**)&vb, g_v);
    cudaGetSymbolAddress((void**)&gb, g_g);

    const size_t BTD = (size_t)BT * Dd;

    static cudaStream_t s2 = nullptr;
    static cudaEvent_t eFork = nullptr, eW = nullptr, eKV = nullptr, eRG = nullptr;
    if (!s2) {
        cudaStreamCreateWithFlags(&s2, cudaStreamNonBlocking);
        cudaEventCreateWithFlags(&eFork, cudaEventDisableTiming);
        cudaEventCreateWithFlags(&eW,    cudaEventDisableTiming);
        cudaEventCreateWithFlags(&eKV,   cudaEventDisableTiming);
        cudaEventCreateWithFlags(&eRG,   cudaEventDisableTiming);
        cudaFuncSetAttribute(gemm4, cudaFuncAttributeMaxDynamicSharedMemorySize, G_SMEM);
        cudaFuncSetAttribute(kA,    cudaFuncAttributeMaxDynamicSharedMemorySize, KA_SMEM);
    }

    // ---- fork: s2 does weight convert + xlast while s0 does kA ----
    cudaEventRecord(eFork, 0);
    cudaStreamWaitEvent(s2, eFork, 0);

    ConvArgs ca;
    ca.s[0] = Wr; ca.h[0] = Wrh;
    ca.s[1] = Wk; ca.h[1] = Wkh;
    ca.s[2] = Wv; ca.h[2] = Wvh;
    ca.s[3] = Wg; ca.h[3] = Wgh;
    ca.s[4] = Wo; ca.h[4] = Woh;
    dim3 wsg((Dd * Dd) / (256 * 4), 5);
    wconv_all<<<wsg, 256, 0, s2>>>(ca);
    xlast_copy<<<(Bb * Dd) / 256, 256, 0, s2>>>(x, out + BTD);

    kA<<<BT / TOK, 256, KA_SMEM, 0>>>(x, shift, tmx, tmw, tmk, tmv, tmr, tmg,
                                      w1, w2, td, dw1, dw2);

    cudaEventRecord(eW, s2);
    cudaStreamWaitEvent(0, eW, 0);

    // ---- gemm(k, v) on s0 (2-pass) ----
    GemmArgs gkv;
    gkv.Ah[0] = xkh; gkv.Al[0] = xkl; gkv.Wh[0] = Wkh; gkv.C[0] = kb; gkv.mode[0] = 0; gkv.nit[0] = 64;
    gkv.Ah[1] = xvh; gkv.Al[1] = xvl; gkv.Wh[1] = Wvh; gkv.C[1] = vb; gkv.mode[1] = 0; gkv.nit[1] = 64;
    dim3 gg2(Dd / 128, BT / 128, 2);
    gemm4<<<gg2, 256, G_SMEM, 0>>>(gkv);

    // fork: s2 runs gemm(r, g) concurrent with pass1/pass2 on s0
    cudaEventRecord(eKV, 0);
    cudaStreamWaitEvent(s2, eKV, 0);

    GemmArgs grg;
    grg.Ah[0] = xrh; grg.Al[0] = xrl; grg.Wh[0] = Wrh; grg.C[0] = rb; grg.mode[0] = 0; grg.nit[0] = 64;
    grg.Ah[1] = xgh; grg.Al[1] = xgl; grg.Wh[1] = Wgh; grg.C[1] = gb; grg.mode[1] = 1; grg.nit[1] = 64;
    gemm4<<<gg2, 256, G_SMEM, s2>>>(grg);

    wkv_pass1<<<Bb * Hh * NCH, 64, 0, 0>>>(kb, vb);
    wkv_pass2<<<Bb * Hh, 64, 0, 0>>>(state0, out + BTD + (size_t)Bb * Dd);

    // join r/g before fused pass3
    cudaEventRecord(eRG, s2);
    cudaStreamWaitEvent(0, eRG, 0);

    wkv_pass3<<<Bb * Hh * NCH, 64, 0, 0>>>(rb, kb, vb, faaaa, gamma, beta);

    // ---- output GEMM: single-pass fp16 (y fp16-rounded; error budget ok) ----
    GemmArgs go_;
    go_.Ah[0] = yh; go_.Al[0] = yl; go_.Wh[0] = Woh; go_.C[0] = out; go_.mode[0] = 0; go_.nit[0] = 32;
    dim3 go(Dd / 128, BT / 128, 1);
    gemm4<<<go, 256, G_SMEM, 0>>>(go_);
}

// round 16
// speedup vs baseline: 1.2263x; 1.2091x over previous
#include <cuda_runtime.h>
#include <cuda_fp16.h>
#include <math.h>
#include <stdint.h>

// ---------------- problem constants ----------------
#define Bb   2
#define Tt   2048
#define Dd   2048
#define Hh   32
#define Kd   64
#define CH   128
#define NCH  (Tt / CH)          // 16
#define BT   (Bb * Tt)          // 4096
#define TOK  4
#define EPSV 6.4e-4f

// ---------------- scratch (device globals, no cudaMalloc) ----------------
__device__ __half g_xkh[BT * Dd];
__device__ __half g_xvh[BT * Dd];
__device__ __half g_xrh[BT * Dd];
__device__ __half g_xgh[BT * Dd];
__device__ __half g_yh [BT * Dd];
__device__ __half g_Wrh[Dd * Dd];
__device__ __half g_Wkh[Dd * Dd];
__device__ __half g_Wvh[Dd * Dd];
__device__ __half g_Wgh[Dd * Dd];
__device__ __half g_Woh[Dd * Dd];
__device__ float g_wd[BT * Dd];
__device__ float g_r [BT * Dd];
__device__ float g_k [BT * Dd];
__device__ float g_v [BT * Dd];
__device__ float g_g [BT * Dd];
__device__ float g_cs[Bb * Hh * NCH * Kd * Kd];
__device__ float g_es[Bb * Hh * NCH * Kd * Kd];
__device__ float g_ws[Bb * Hh * NCH * Kd];

// ---------------- PTX helpers ----------------
#define LDSM4(r0,r1,r2,r3,addr) \
    asm volatile("ldmatrix.sync.aligned.m8n8.x4.shared.b16 {%0,%1,%2,%3}, [%4];" \
        : "=r"(r0),"=r"(r1),"=r"(r2),"=r"(r3) : "r"(addr))

#define MMA16816F(d,a,b) \
    asm volatile("mma.sync.aligned.m16n8k16.row.col.f32.f16.f16.f32 " \
        "{%0,%1,%2,%3},{%4,%5,%6,%7},{%8,%9},{%0,%1,%2,%3};" \
        : "+f"(d[0]),"+f"(d[1]),"+f"(d[2]),"+f"(d[3]) \
        : "r"(a[0]),"r"(a[1]),"r"(a[2]),"r"(a[3]),"r"(b[0]),"r"(b[1]))

#define CP_ASYNC16(dst, src) \
    asm volatile("cp.async.cg.shared.global [%0], [%1], 16;" :: "r"(dst), "l"(src) : "memory")
#define CP_COMMIT() asm volatile("cp.async.commit_group;" ::: "memory")
#define CP_WAIT1()  asm volatile("cp.async.wait_group 1;" ::: "memory")

// =====================================================================
// Batched tensor-core GEMM (mma.sync), single-pass fp16: C = Ah.Wh
// 128x128 CTA tile, BK=64, 3-stage cp.async pipeline, 8 warps.
// =====================================================================
#define G_STAGE 32768
#define G_SMEM  (3 * G_STAGE)
#define G_NIT   32

struct GemmArgs {
    const __half* Ah[4];
    const __half* Wh[4];
    float* C[4];
    int mode[4];
};

__device__ __forceinline__ void issue_chunk(
    int nx, uint32_t sbase, int m0, int n0, int tid,
    const __half* Ah, const __half* Wh)
{
    const int kk = nx << 6;
    uint32_t sa = sbase + (nx % 3) * G_STAGE;
    uint32_t sb = sa + 16384;
    #pragma unroll
    for (int i = 0; i < 4; i++) {
        int ch = tid + i * 256;
        int r = ch >> 3, c = ch & 7;
        uint32_t soff = r * 128 + ((c ^ (r & 7)) << 4);
        CP_ASYNC16(sa + soff, Ah + (size_t)(m0 + r) * Dd + kk + c * 8);
        CP_ASYNC16(sb + soff, Wh + (size_t)(n0 + r) * Dd + kk + c * 8);
    }
}

__global__ void __launch_bounds__(256) gemm4(GemmArgs ga)
{
    extern __shared__ char gsm[];
    uint32_t sbase;
    asm("{ .reg .u64 t; cvta.to.shared.u64 t, %1; cvt.u32.u64 %0, t; }"
        : "=r"(sbase) : "l"(gsm));

    const int z = blockIdx.z;
    const __half* Ahp = ga.Ah[z];
    const __half* Whp = ga.Wh[z];
    float* Cp = ga.C[z];
    const int mode = ga.mode[z];

    const int tid  = threadIdx.x;
    const int lane = tid & 31;
    const int w    = tid >> 5;
    const int wm   = w >> 2;
    const int wn   = w & 3;
    const int m0   = blockIdx.y * 128;
    const int n0   = blockIdx.x * 128;

    const int rlo = (lane & 7) + ((lane >> 3) & 1) * 8;
    const int lg  = lane >> 4;

    int arow[4], asw[4];
    #pragma unroll
    for (int i = 0; i < 4; i++) {
        int r = wm * 64 + i * 16 + rlo;
        arow[i] = r * 128;
        asw[i]  = r & 7;
    }
    int brow[2], bsw[2];
    #pragma unroll
    for (int jp = 0; jp < 2; jp++) {
        int r = wn * 32 + jp * 16 + rlo;
        brow[jp] = r * 128;
        bsw[jp]  = r & 7;
    }

    float acc[4][4][4];
    #pragma unroll
    for (int i = 0; i < 4; i++)
        #pragma unroll
        for (int j = 0; j < 4; j++)
            #pragma unroll
            for (int q = 0; q < 4; q++) acc[i][j][q] = 0.f;

    issue_chunk(0, sbase, m0, n0, tid, Ahp, Whp); CP_COMMIT();
    issue_chunk(1, sbase, m0, n0, tid, Ahp, Whp); CP_COMMIT();

    for (int it = 0; it < G_NIT; it++) {
        CP_WAIT1();
        __syncthreads();

        if (it + 2 < G_NIT)
            issue_chunk(it + 2, sbase, m0, n0, tid, Ahp, Whp);
        CP_COMMIT();

        uint32_t abase = sbase + (it % 3) * G_STAGE;
        uint32_t bbase = abase + 16384;
        #pragma unroll
        for (int ks = 0; ks < 4; ks++) {
            const int cc = ks * 2 + lg;
            uint32_t a[4][4], b[4][2];
            #pragma unroll
            for (int i = 0; i < 4; i++) {
                uint32_t addr = abase + arow[i] + ((cc ^ asw[i]) << 4);
                LDSM4(a[i][0], a[i][1], a[i][2], a[i][3], addr);
            }
            #pragma unroll
            for (int jp = 0; jp < 2; jp++) {
                uint32_t addr = bbase + brow[jp] + ((cc ^ bsw[jp]) << 4);
                uint32_t t0, t1, t2, t3;
                LDSM4(t0, t1, t2, t3, addr);
                b[2 * jp][0] = t0; b[2 * jp + 1][0] = t1;
                b[2 * jp][1] = t2; b[2 * jp + 1][1] = t3;
            }
            #pragma unroll
            for (int i = 0; i < 4; i++)
                #pragma unroll
                for (int j = 0; j < 4; j++)
                    MMA16816F(acc[i][j], a[i], b[j]);
        }
    }

    #pragma unroll
    for (int i = 0; i < 4; i++) {
        int mr = m0 + wm * 64 + i * 16 + (lane >> 2);
        #pragma unroll
        for (int j = 0; j < 4; j++) {
            int nc = n0 + wn * 32 + j * 8 + (lane & 3) * 2;
            float v0 = acc[i][j][0], v1 = acc[i][j][1];
            float v2 = acc[i][j][2], v3 = acc[i][j][3];
            if (mode == 1) {
                v0 = v0 / (1.f + expf(-v0));
                v1 = v1 / (1.f + expf(-v1));
                v2 = v2 / (1.f + expf(-v2));
                v3 = v3 / (1.f + expf(-v3));
            }
            *(float2*)&Cp[(size_t)mr * Dd + nc]       = make_float2(v0, v1);
            *(float2*)&Cp[(size_t)(mr + 8) * Dd + nc] = make_float2(v2, v3);
        }
    }
}

// =====================================================================
// Kernel A: token mixing (R9 shape; hi-only fp16 stores)
// =====================================================================
#define KA_SMEM ((4*2048 + 8*4*160 + 4*160 + 4*64) * 4)   // 56832 B

__global__ void __launch_bounds__(256) kA(
    const float* __restrict__ x,   const float* __restrict__ shift,
    const float* __restrict__ tmx, const float* __restrict__ tmw,
    const float* __restrict__ tmk, const float* __restrict__ tmv,
    const float* __restrict__ tmr, const float* __restrict__ tmg,
    const float* __restrict__ w1,  const float* __restrict__ w2,
    const float* __restrict__ td,  const float* __restrict__ dw1,
    const float* __restrict__ dw2)
{
    extern __shared__ float sm[];
    float* sxxx = sm;                       // 4*2048
    float* ps   = sm + 4 * 2048;            // 8*4*160
    float* sst  = ps + 8 * 4 * 160;         // 4*160
    float* ssh  = sst + 4 * 160;            // 4*64

    const int tid  = threadIdx.x;
    const int wqid = tid >> 5;
    const int lane = tid & 31;
    const int t0   = blockIdx.x * TOK;

    for (int tok = 0; tok < TOK; tok++) {
        int gt = t0 + tok;
        int b = gt / Tt, tt = gt % Tt;
        const float* xrow = x + (size_t)gt * Dd;
        const float* xprv = (tt == 0) ? (shift + (size_t)b * Dd)
                                      : (x + (size_t)(gt - 1) * Dd);
        for (int d = tid; d < Dd; d += 256) {
            float xv_ = xrow[d];
            sxxx[tok * Dd + d] = xv_ + (xprv[d] - xv_) * tmx[d];
        }
    }
    __syncthreads();

    {
        float acc[5][TOK];
        #pragma unroll
        for (int g = 0; g < 5; g++)
            #pragma unroll
            for (int t = 0; t < TOK; t++) acc[g][t] = 0.f;
        const int d0 = wqid * 256;
        for (int dd = 0; dd < 256; dd++) {
            int d = d0 + dd;
            float xv[TOK];
            #pragma unroll
            for (int t = 0; t < TOK; t++) xv[t] = sxxx[t * Dd + d];
            #pragma unroll
            for (int g = 0; g < 5; g++) {
                float w1v = w1[d * 160 + g * 32 + lane];
                #pragma unroll
                for (int t = 0; t < TOK; t++) acc[g][t] += xv[t] * w1v;
            }
        }
        #pragma unroll
        for (int g = 0; g < 5; g++)
            #pragma unroll
            for (int t = 0; t < TOK; t++)
                ps[(wqid * TOK + t) * 160 + g * 32 + lane] = acc[g][t];
        __syncthreads();
        for (int idx = tid; idx < TOK * 160; idx += 256) {
            int t = idx / 160, j = idx % 160;
            float s = 0.f;
            #pragma unroll
            for (int w8 = 0; w8 < 8; w8++) s += ps[(w8 * TOK + t) * 160 + j];
            sst[t * 160 + j] = tanhf(s);
        }
        __syncthreads();
    }

    for (int d = tid; d < Dd; d += 256) {
        float macc[TOK][5];
        #pragma unroll
        for (int t = 0; t < TOK; t++)
            #pragma unroll
            for (int g = 0; g < 5; g++) macc[t][g] = 0.f;

        #pragma unroll
        for (int g = 0; g < 5; g++) {
            for (int j32 = 0; j32 < 32; j32++) {
                int j = g * 32 + j32;
                float w2v = w2[(size_t)j * Dd + d];
                #pragma unroll
                for (int t = 0; t < TOK; t++) macc[t][g] += sst[t * 160 + j] * w2v;
            }
        }
        float twv = tmw[d], tkv = tmk[d], tvv = tmv[d], trv = tmr[d], tgv = tmg[d];
        #pragma unroll
        for (int tok = 0; tok < TOK; tok++) {
            int gt = t0 + tok;
            int b = gt / Tt, tt = gt % Tt;
            float xv_ = x[(size_t)gt * Dd + d];
            float xpv = (tt == 0) ? shift[(size_t)b * Dd + d]
                                  : x[(size_t)(gt - 1) * Dd + d];
            float dx = xpv - xv_;
            size_t o = (size_t)gt * Dd + d;
            g_xkh[o] = __float2half_rn(xv_ + dx * (tkv + macc[tok][1]));
            g_xvh[o] = __float2half_rn(xv_ + dx * (tvv + macc[tok][2]));
            g_xrh[o] = __float2half_rn(xv_ + dx * (trv + macc[tok][3]));
            g_xgh[o] = __float2half_rn(xv_ + dx * (tgv + macc[tok][4]));
            sxxx[tok * Dd + d] = xv_ + dx * (twv + macc[tok][0]);
        }
    }
    __syncthreads();

    {
        float acc[2][TOK];
        #pragma unroll
        for (int g = 0; g < 2; g++)
            #pragma unroll
            for (int t = 0; t < TOK; t++) acc[g][t] = 0.f;
        const int d0 = wqid * 256;
        for (int dd = 0; dd < 256; dd++) {
            int d = d0 + dd;
            float xv[TOK];
            #pragma unroll
            for (int t = 0; t < TOK; t++) xv[t] = sxxx[t * Dd + d];
            #pragma unroll
            for (int g = 0; g < 2; g++) {
                float w1v = dw1[d * 64 + g * 32 + lane];
                #pragma unroll
                for (int t = 0; t < TOK; t++) acc[g][t] += xv[t] * w1v;
            }
        }
        #pragma unroll
        for (int g = 0; g < 2; g++)
            #pragma unroll
            for (int t = 0; t < TOK; t++)
                ps[(wqid * TOK + t) * 64 + g * 32 + lane] = acc[g][t];
        __syncthreads();
        for (int idx = tid; idx < TOK * 64; idx += 256) {
            int t = idx / 64, j = idx % 64;
            float s = 0.f;
            #pragma unroll
            for (int w8 = 0; w8 < 8; w8++) s += ps[(w8 * TOK + t) * 64 + j];
            ssh[t * 64 + j] = tanhf(s);
        }
        __syncthreads();
    }

    for (int d = tid; d < Dd; d += 256) {
        float acc[TOK];
        #pragma unroll
        for (int t = 0; t < TOK; t++) acc[t] = 0.f;
        for (int j = 0; j < 64; j++) {
            float w2v = dw2[(size_t)j * Dd + d];
            #pragma unroll
            for (int t = 0; t < TOK; t++) acc[t] += ssh[t * 64 + j] * w2v;
        }
        float tdv = td[d];
        #pragma unroll
        for (int t = 0; t < TOK; t++) {
            float wdv = fmaxf(expf(-expf(tdv + acc[t])), 0.005f);
            g_wd[(size_t)(t0 + t) * Dd + d] = wdv;
        }
    }
}

// =====================================================================
// Weight convert: fp32 -> fp16
// =====================================================================
struct ConvArgs {
    const float* s[5];
    __half* h[5];
};

__global__ void __launch_bounds__(256) wconv_all(ConvArgs ca)
{
    const int z = blockIdx.y;
    const float* src = ca.s[z];
    __half* hi = ca.h[z];
    int i = (blockIdx.x * 256 + threadIdx.x) * 4;
    float4 v = *(const float4*)(src + i);
    __half2* hp = (__half2*)(hi + i);
    hp[0] = __floats2half2_rn(v.x, v.y);
    hp[1] = __floats2half2_rn(v.z, v.w);
}

// =====================================================================
// WKV pass 1 (CH=128, double-buffered smem, 1 sync/step, prefetch)
// =====================================================================
__global__ void __launch_bounds__(64) wkv_pass1(
    const float* __restrict__ kbuf, const float* __restrict__ vbuf)
{
    const int cid = blockIdx.x;
    const int n  = cid % NCH;
    const int bh = cid / NCH;
    const int h  = bh % Hh;
    const int b  = bh / Hh;
    const int j  = threadIdx.x;

    __shared__ float2 sp[2][64];
    float S[64];
    #pragma unroll
    for (int k = 0; k < 64; k++) S[k] = 0.f;
    float wsa = 1.f;

    size_t base = ((size_t)(b * Tt + n * CH)) * Dd + h * 64 + j;
    float kk = kbuf[base];
    float wd = g_wd[base];
    float vj = vbuf[base];

    for (int tt = 0; tt < CH; tt++) {
        const int buf = tt & 1;
        sp[buf][j] = make_float2(kk, wd);
        wsa *= wd;
        __syncthreads();
        if (tt + 1 < CH) {
            size_t o = base + (size_t)(tt + 1) * Dd;
            kk = kbuf[o];
            wd = g_wd[o];
        }
        float vc = vj;
        if (tt + 1 < CH) vj = vbuf[base + (size_t)(tt + 1) * Dd];
        const float4* p4 = (const float4*)sp[buf];
        #pragma unroll
        for (int kq = 0; kq < 32; kq++) {
            float4 q = p4[kq];
            S[2 * kq]     = q.y * S[2 * kq]     + q.x * vc;
            S[2 * kq + 1] = q.w * S[2 * kq + 1] + q.z * vc;
        }
    }
    float* cs = g_cs + (size_t)cid * 4096;
    #pragma unroll
    for (int k = 0; k < 64; k++) cs[k * 64 + j] = S[k];
    g_ws[cid * 64 + j] = wsa;
}

// =====================================================================
// WKV pass 2: scan over chunks
// =====================================================================
__global__ void __launch_bounds__(64) wkv_pass2(
    const float* __restrict__ state0, float* __restrict__ out_state)
{
    const int bh = blockIdx.x;
    const int j  = threadIdx.x;
    __shared__ float sws[64];

    float S[64];
    const float* s0 = state0 + (size_t)bh * 4096;
    #pragma unroll
    for (int k = 0; k < 64; k++) S[k] = s0[k * 64 + j];

    for (int n = 0; n < NCH; n++) {
        size_t cid = (size_t)bh * NCH + n;
        float* es = g_es + cid * 4096;
        #pragma unroll
        for (int k = 0; k < 64; k++) es[k * 64 + j] = S[k];
        sws[j] = g_ws[cid * 64 + j];
        __syncthreads();
        const float* cs = g_cs + cid * 4096;
        #pragma unroll
        for (int k = 0; k < 64; k++)
            S[k] = S[k] * sws[k] + cs[k * 64 + j];
        __syncthreads();
    }
    float* os = out_state + (size_t)bh * 4096;
    #pragma unroll
    for (int k = 0; k < 64; k++) os[k * 64 + j] = S[k];
}

// =====================================================================
// WKV pass 3 FUSED with GroupNorm*gate, software-pipelined (1 sync/step)
// =====================================================================
__global__ void __launch_bounds__(64) wkv_pass3(
    const float* __restrict__ rbuf, const float* __restrict__ kbuf,
    const float* __restrict__ vbuf, const float* __restrict__ faaaa,
    const float* __restrict__ gamma, const float* __restrict__ beta)
{
    const int cid = blockIdx.x;
    const int n  = cid % NCH;
    const int bh = cid / NCH;
    const int h  = bh % Hh;
    const int b  = bh / Hh;
    const int j  = threadIdx.x;
    const int wq = j >> 5;
    const int lane = j & 31;

    __shared__ float4 sq[2][64];
    __shared__ float2 sred[2][2];

    float S[64];
    const float* es = g_es + (size_t)cid * 4096;
    #pragma unroll
    for (int k = 0; k < 64; k++) S[k] = es[k * 64 + j];
    const float uj  = faaaa[h * 64 + j];
    const float gam = gamma[h * 64 + j];
    const float bet = beta [h * 64 + j];

    size_t base = ((size_t)(b * Tt + n * CH)) * Dd + h * 64 + j;
    float kk = kbuf[base];
    float wd = g_wd[base];
    float rr = rbuf[base];
    float vj = vbuf[base];
    float gg = g_g[base];

    float py = 0.f, ps1 = 0.f, ps2 = 0.f, pg = 0.f;
    size_t pocur = 0;

    for (int tt = 0; tt < CH; tt++) {
        const int buf = tt & 1;
        sq[buf][j] = make_float4(kk, wd, rr, rr * uj * kk);
        if (tt > 0 && lane == 0) sred[buf ^ 1][wq] = make_float2(ps1, ps2);
        __syncthreads();

        if (tt > 0) {
            float ts1 = sred[buf ^ 1][0].x + sred[buf ^ 1][1].x;
            float ts2 = sred[buf ^ 1][0].y + sred[buf ^ 1][1].y;
            float mu  = ts1 * (1.f / 64.f);
            float var = ts2 * (1.f / 64.f) - mu * mu;
            float inv = rsqrtf(var + EPSV);
            float yo  = ((py - mu) * inv * gam + bet) * pg;
            g_yh[pocur] = __float2half_rn(yo);
        }

        size_t ocur = base + (size_t)tt * Dd;
        float vc = vj, gc = gg;
        if (tt + 1 < CH) {
            size_t o = ocur + Dd;
            kk = kbuf[o];
            wd = g_wd[o];
            rr = rbuf[o];
            vj = vbuf[o];
            gg = g_g[o];
        }
        float outv = 0.f, rk = 0.f;
        const float4* qb = sq[buf];
        #pragma unroll
        for (int k = 0; k < 64; k++) {
            float4 q = qb[k];
            outv += q.z * S[k];
            rk   += q.w;
            S[k] = q.y * S[k] + q.x * vc;
        }
        float y = outv + rk * vc;

        float s1 = y, s2 = y * y;
        #pragma unroll
        for (int off = 16; off > 0; off >>= 1) {
            s1 += __shfl_xor_sync(0xffffffffu, s1, off);
            s2 += __shfl_xor_sync(0xffffffffu, s2, off);
        }
        py = y; ps1 = s1; ps2 = s2; pg = gc; pocur = ocur;
    }

    if (lane == 0) sred[(CH - 1) & 1][wq] = make_float2(ps1, ps2);
    __syncthreads();
    {
        const int pb = (CH - 1) & 1;
        float ts1 = sred[pb][0].x + sred[pb][1].x;
        float ts2 = sred[pb][0].y + sred[pb][1].y;
        float mu  = ts1 * (1.f / 64.f);
        float var = ts2 * (1.f / 64.f) - mu * mu;
        float inv = rsqrtf(var + EPSV);
        float yo  = ((py - mu) * inv * gam + bet) * pg;
        g_yh[pocur] = __float2half_rn(yo);
    }
}

__global__ void __launch_bounds__(256) xlast_copy(
    const float* __restrict__ x, float* __restrict__ dst)
{
    int i = blockIdx.x * 256 + threadIdx.x;
    int b = i / Dd, d = i % Dd;
    dst[i] = x[((size_t)b * Tt + Tt - 1) * Dd + d];
}

// =====================================================================
// launch — two-stream schedule, all GEMMs single-pass fp16
// =====================================================================
extern "C" void kernel_launch(void* const* d_in, const int* in_sizes, int n_in,
                              void* d_out, int out_size)
{
    const float* x      = (const float*)d_in[0];
    const float* shift  = (const float*)d_in[1];
    const float* state0 = (const float*)d_in[2];
    const float* tmx    = (const float*)d_in[3];
    const float* tmw    = (const float*)d_in[4];
    const float* tmk    = (const float*)d_in[5];
    const float* tmv    = (const float*)d_in[6];
    const float* tmr    = (const float*)d_in[7];
    const float* tmg    = (const float*)d_in[8];
    const float* w1     = (const float*)d_in[9];
    const float* w2     = (const float*)d_in[10];
    const float* td     = (const float*)d_in[11];
    const float* dw1    = (const float*)d_in[12];
    const float* dw2    = (const float*)d_in[13];
    const float* faaaa  = (const float*)d_in[14];
    const float* Wr     = (const float*)d_in[15];
    const float* Wk     = (const float*)d_in[16];
    const float* Wv     = (const float*)d_in[17];
    const float* Wg     = (const float*)d_in[18];
    const float* Wo     = (const float*)d_in[19];
    const float* gamma  = (const float*)d_in[20];
    const float* beta   = (const float*)d_in[21];
    float* out = (float*)d_out;

    __half *xkh,*xvh,*xrh,*xgh,*yh;
    __half *Wrh,*Wkh,*Wvh,*Wgh,*Woh;
    float *rb,*kb,*vb,*gb;
    cudaGetSymbolAddress((void**)&xkh, g_xkh);
    cudaGetSymbolAddress((void**)&xvh, g_xvh);
    cudaGetSymbolAddress((void**)&xrh, g_xrh);
    cudaGetSymbolAddress((void**)&xgh, g_xgh);
    cudaGetSymbolAddress((void**)&yh,  g_yh);
    cudaGetSymbolAddress((void**)&Wrh, g_Wrh);
    cudaGetSymbolAddress((void**)&Wkh, g_Wkh);
    cudaGetSymbolAddress((void**)&Wvh, g_Wvh);
    cudaGetSymbolAddress((void**)&Wgh, g_Wgh);
    cudaGetSymbolAddress((void**)&Woh, g_Woh);
    cudaGetSymbolAddress((void**)&rb, g_r);
    cudaGetSymbolAddress((void**)&kb, g_k);
    cudaGetSymbolAddress((void**)&vb, g_v);
    cudaGetSymbolAddress((void**)&gb, g_g);

    const size_t BTD = (size_t)BT * Dd;

    static cudaStream_t s2 = nullptr;
    static cudaEvent_t eFork = nullptr, eW = nullptr, eKV = nullptr, eRG = nullptr;
    if (!s2) {
        cudaStreamCreateWithFlags(&s2, cudaStreamNonBlocking);
        cudaEventCreateWithFlags(&eFork, cudaEventDisableTiming);
        cudaEventCreateWithFlags(&eW,    cudaEventDisableTiming);
        cudaEventCreateWithFlags(&eKV,   cudaEventDisableTiming);
        cudaEventCreateWithFlags(&eRG,   cudaEventDisableTiming);
        cudaFuncSetAttribute(gemm4, cudaFuncAttributeMaxDynamicSharedMemorySize, G_SMEM);
        cudaFuncSetAttribute(kA,    cudaFuncAttributeMaxDynamicSharedMemorySize, KA_SMEM);
    }

    // ---- fork: s2 does weight convert + xlast while s0 does kA ----
    cudaEventRecord(eFork, 0);
    cudaStreamWaitEvent(s2, eFork, 0);

    ConvArgs ca;
    ca.s[0] = Wr; ca.h[0] = Wrh;
    ca.s[1] = Wk; ca.h[1] = Wkh;
    ca.s[2] = Wv; ca.h[2] = Wvh;
    ca.s[3] = Wg; ca.h[3] = Wgh;
    ca.s[4] = Wo; ca.h[4] = Woh;
    dim3 wsg((Dd * Dd) / (256 * 4), 5);
    wconv_all<<<wsg, 256, 0, s2>>>(ca);
    xlast_copy<<<(Bb * Dd) / 256, 256, 0, s2>>>(x, out + BTD);

    kA<<<BT / TOK, 256, KA_SMEM, 0>>>(x, shift, tmx, tmw, tmk, tmv, tmr, tmg,
                                      w1, w2, td, dw1, dw2);

    cudaEventRecord(eW, s2);
    cudaStreamWaitEvent(0, eW, 0);

    // ---- gemm(k, v) on s0 ----
    GemmArgs gkv;
    gkv.Ah[0] = xkh; gkv.Wh[0] = Wkh; gkv.C[0] = kb; gkv.mode[0] = 0;
    gkv.Ah[1] = xvh; gkv.Wh[1] = Wvh; gkv.C[1] = vb; gkv.mode[1] = 0;
    dim3 gg2(Dd / 128, BT / 128, 2);
    gemm4<<<gg2, 256, G_SMEM, 0>>>(gkv);

    // fork: s2 runs gemm(r, g) concurrent with pass1/pass2 on s0
    cudaEventRecord(eKV, 0);
    cudaStreamWaitEvent(s2, eKV, 0);

    GemmArgs grg;
    grg.Ah[0] = xrh; grg.Wh[0] = Wrh; grg.C[0] = rb; grg.mode[0] = 0;
    grg.Ah[1] = xgh; grg.Wh[1] = Wgh; grg.C[1] = gb; grg.mode[1] = 1;
    gemm4<<<gg2, 256, G_SMEM, s2>>>(grg);

    wkv_pass1<<<Bb * Hh * NCH, 64, 0, 0>>>(kb, vb);
    wkv_pass2<<<Bb * Hh, 64, 0, 0>>>(state0, out + BTD + (size_t)Bb * Dd);

    // join r/g before fused pass3
    cudaEventRecord(eRG, s2);
    cudaStreamWaitEvent(0, eRG, 0);

    wkv_pass3<<<Bb * Hh * NCH, 64, 0, 0>>>(rb, kb, vb, faaaa, gamma, beta);

    // ---- output GEMM ----
    GemmArgs go_;
    go_.Ah[0] = yh; go_.Wh[0] = Woh; go_.C[0] = out; go_.mode[0] = 0;
    dim3 go(Dd / 128, BT / 128, 1);
    gemm4<<<go, 256, G_SMEM, 0>>>(go_);
}